// round 15
// baseline (speedup 1.0000x reference)
#include <cuda_runtime.h>
#include <math.h>

// ---------------- scratch ----------------
__device__ float g_h1[16777216];      // 32768*512 (reused; also 4096*2048)
__device__ float g_df[16777216];      // 32768*512
__device__ float g_ef[37748736];      // 32768*1152 (padded rows; also split-K partials)
__device__ float g_coords[65536];     // 32768*2
__device__ float g_imp[32768];
__device__ int   g_top[4096];         // 8*512
__device__ float g_pos[8192];         // 8*512*2
__device__ float g_states[4194304];   // 4096*1024
__device__ float g_proj[2097152];     // 4096*512
__device__ float g_We2p[589824];      // 512*1152 padded We2
__device__ float g_be2p[1152];        // padded be2
__device__ float g_ex[409600];        // 8*100*512 separable exp table (x)
__device__ float g_ey[409600];        // 8*100*512 separable exp table (y)

__device__ __forceinline__ float gelu_f(float x) {
    return 0.5f * x * (1.0f + erff(x * 0.70710678118654752440f));
}

// ---- packed fp32x2 helpers (bit-exact fp32) ----
__device__ __forceinline__ unsigned long long pack2(float x) {
    unsigned long long r;
    asm("mov.b64 %0, {%1, %1};" : "=l"(r) : "f"(x));
    return r;
}
__device__ __forceinline__ void fma2(unsigned long long& d,
                                     unsigned long long a,
                                     unsigned long long b) {
    asm("fma.rn.f32x2 %0, %1, %2, %0;" : "+l"(d) : "l"(a), "l"(b));
}
__device__ __forceinline__ float2 unpack2(unsigned long long p) {
    float2 f;
    asm("mov.b64 {%0, %1}, %2;" : "=f"(f.x), "=f"(f.y) : "l"(p));
    return f;
}

// ---------------- pad We2 (512,1027) -> (512,1152), be2 -> 1152 ----------------
__global__ void __launch_bounds__(256) padB_k(const float* __restrict__ src,
                                              float* __restrict__ dst,
                                              const float* __restrict__ bsrc,
                                              float* __restrict__ bdst)
{
    int i = blockIdx.x * 256 + threadIdx.x;
    if (i < 1152) bdst[i] = (i < 1027) ? bsrc[i] : 0.0f;
    if (i >= 512 * 1152) return;
    int r = i / 1152, c = i - r * 1152;
    dst[i] = (c < 1027) ? src[r * 1027 + c] : 0.0f;
}

// ---------------- tiled fp32 GEMM, 128x64x16, 8x4/thread, FFMA2, double-buffered ----------------
// 3 CTAs/SM (6 warps/SMSP) for latency hiding; acc2 = 32 regs.
// EPI: 0 = +bias, 1 = gelu(+bias), 2 = gelu(+bias + coords@wtop), 3 = split-K x2 raw partial
#define GEMM_PREFETCH(KN)                                                                       \
    do {                                                                                        \
        ra0 = *reinterpret_cast<const float4*>(A + (size_t)(bm + rA0) * lda + (KN) + cA4 * 4);  \
        ra1 = *reinterpret_cast<const float4*>(A + (size_t)(bm + rA0 + 64) * lda + (KN) + cA4 * 4); \
        rb  = *reinterpret_cast<const float4*>(B + (size_t)((KN) + rBr) * ldb + bn + cBc * 4);  \
    } while (0)

#define GEMM_STORE(BUF)                                                                         \
    do {                                                                                        \
        As2[BUF][cA4 * 4 + 0][rA0] = pack2(ra0.x);                                              \
        As2[BUF][cA4 * 4 + 1][rA0] = pack2(ra0.y);                                              \
        As2[BUF][cA4 * 4 + 2][rA0] = pack2(ra0.z);                                              \
        As2[BUF][cA4 * 4 + 3][rA0] = pack2(ra0.w);                                              \
        As2[BUF][cA4 * 4 + 0][rA0 + 64] = pack2(ra1.x);                                         \
        As2[BUF][cA4 * 4 + 1][rA0 + 64] = pack2(ra1.y);                                         \
        As2[BUF][cA4 * 4 + 2][rA0 + 64] = pack2(ra1.z);                                         \
        As2[BUF][cA4 * 4 + 3][rA0 + 64] = pack2(ra1.w);                                         \
        *reinterpret_cast<float4*>(&Bs[BUF][rBr][cBc * 4]) = rb;                                \
    } while (0)

#define GEMM_COMPUTE(BUF)                                                                       \
    do {                                                                                        \
        _Pragma("unroll")                                                                       \
        for (int k = 0; k < 16; k++) {                                                          \
            ulonglong2 A0 = *reinterpret_cast<const ulonglong2*>(&As2[BUF][k][row]);            \
            ulonglong2 A1 = *reinterpret_cast<const ulonglong2*>(&As2[BUF][k][row + 2]);        \
            ulonglong2 A2 = *reinterpret_cast<const ulonglong2*>(&As2[BUF][k][row + 4]);        \
            ulonglong2 A3 = *reinterpret_cast<const ulonglong2*>(&As2[BUF][k][row + 6]);        \
            ulonglong2 Bp = *reinterpret_cast<const ulonglong2*>(&Bs[BUF][k][tx * 4]);          \
            fma2(acc2[0][0], A0.x, Bp.x); fma2(acc2[0][1], A0.x, Bp.y);                         \
            fma2(acc2[1][0], A0.y, Bp.x); fma2(acc2[1][1], A0.y, Bp.y);                         \
            fma2(acc2[2][0], A1.x, Bp.x); fma2(acc2[2][1], A1.x, Bp.y);                         \
            fma2(acc2[3][0], A1.y, Bp.x); fma2(acc2[3][1], A1.y, Bp.y);                         \
            fma2(acc2[4][0], A2.x, Bp.x); fma2(acc2[4][1], A2.x, Bp.y);                         \
            fma2(acc2[5][0], A2.y, Bp.x); fma2(acc2[5][1], A2.y, Bp.y);                         \
            fma2(acc2[6][0], A3.x, Bp.x); fma2(acc2[6][1], A3.x, Bp.y);                         \
            fma2(acc2[7][0], A3.y, Bp.x); fma2(acc2[7][1], A3.y, Bp.y);                         \
        }                                                                                       \
    } while (0)

template<int EPI>
__global__ void __launch_bounds__(256, 3) gemm_k(
    const float* __restrict__ A, const float* __restrict__ B,
    const float* __restrict__ bias, float* __restrict__ C,
    int M, int N, int K, int lda, int ldb,
    const float* __restrict__ coords, const float* __restrict__ wtop)
{
    __shared__ __align__(16) unsigned long long As2[2][16][130];
    __shared__ __align__(16) float Bs[2][16][68];

    const int tid = threadIdx.x;
    int bm, bn;
    if (EPI == 3) {
        const int half = blockIdx.y >> 5;
        bm = (blockIdx.y & 31) * 128;
        bn = blockIdx.x * 64;
        A += (size_t)half * 1024;                 // lda covers the full row
        B += (size_t)half * 1024 * ldb;
        C += (size_t)half * 2097152;              // 4096*512 partial stride
    } else {
        bm = blockIdx.y * 128;
        bn = blockIdx.x * 64;
    }
    const int tx  = tid & 15;          // col group: cols bn + tx*4 .. +3
    const int ty  = tid >> 4;          // row group: rows bm + ty*8 .. +7
    const int row = ty * 8;

    unsigned long long acc2[8][2];
    #pragma unroll
    for (int i = 0; i < 8; i++) { acc2[i][0] = 0ULL; acc2[i][1] = 0ULL; }

    const int rA0 = tid >> 2;          // 0..63 (and +64)
    const int cA4 = tid & 3;
    const int rBr = tid >> 4;          // 0..15 B row
    const int cBc = tid & 15;          // 0..15 B col4

    float4 ra0, ra1, rb;

    GEMM_PREFETCH(0);
    GEMM_STORE(0);
    __syncthreads();

    const int T = K >> 4;        // always even (32 or 64)
    for (int t = 0; t < T; t += 2) {
        GEMM_PREFETCH((t + 1) << 4);
        GEMM_COMPUTE(0);
        GEMM_STORE(1);
        __syncthreads();
        if (t + 2 < T) {
            GEMM_PREFETCH((t + 2) << 4);
            GEMM_COMPUTE(1);
            GEMM_STORE(0);
            __syncthreads();
        } else {
            GEMM_COMPUTE(1);
        }
    }

    float acc[8][4];
    #pragma unroll
    for (int i = 0; i < 8; i++) {
        float2 t0 = unpack2(acc2[i][0]);
        float2 t1 = unpack2(acc2[i][1]);
        acc[i][0] = t0.x; acc[i][1] = t0.y; acc[i][2] = t1.x; acc[i][3] = t1.y;
    }

    float bs[4], w0[4], w1[4];
    #pragma unroll
    for (int jj = 0; jj < 4; jj++) {
        int n = bn + tx * 4 + jj;
        bs[jj] = (EPI == 3) ? 0.0f : bias[n];
        if (EPI == 2) { w0[jj] = wtop[n]; w1[jj] = wtop[512 + n]; }
    }

    #pragma unroll
    for (int i = 0; i < 8; i++) {
        int gm = bm + row + i;
        float c0 = 0.0f, c1 = 0.0f;
        if (EPI == 2) { c0 = coords[(size_t)gm * 2]; c1 = coords[(size_t)gm * 2 + 1]; }
        float t[4];
        #pragma unroll
        for (int jj = 0; jj < 4; jj++) {
            float val = acc[i][jj] + bs[jj];
            if (EPI == 2) val += c0 * w0[jj] + c1 * w1[jj];
            if (EPI == 1 || EPI == 2) val = gelu_f(val);
            t[jj] = val;
        }
        float4 v; v.x = t[0]; v.y = t[1]; v.z = t[2]; v.w = t[3];
        *reinterpret_cast<float4*>(C + (size_t)gm * N + bn + tx * 4) = v;
    }
}

// ---------------- split-K reduce for stage 11: proj = p0 + p1 + bo2 ----------------
__global__ void __launch_bounds__(256) reduce10_k(
    const float* __restrict__ parts, const float* __restrict__ bias,
    float* __restrict__ proj)
{
    int i4 = blockIdx.x * 256 + threadIdx.x;        // float4 index over 4096*512
    if (i4 >= 524288) return;
    const float4* p0 = reinterpret_cast<const float4*>(parts);
    const float4* p1 = reinterpret_cast<const float4*>(parts + 2097152);
    const float4* b4 = reinterpret_cast<const float4*>(bias);
    float4 a = p0[i4];
    float4 b = p1[i4];
    float4 c = b4[i4 & 127];
    float4 v;
    v.x = a.x + b.x + c.x;
    v.y = a.y + b.y + c.y;
    v.z = a.z + b.z + c.z;
    v.w = a.w + b.w + c.w;
    reinterpret_cast<float4*>(proj)[i4] = v;
}

// ---------------- coords: (32768,512) @ (512,2) + bc, float4 ----------------
__global__ void __launch_bounds__(256) coords_k(
    const float* __restrict__ df, const float* __restrict__ Wc,
    const float* __restrict__ bc, float* __restrict__ coords)
{
    int r    = blockIdx.x * 8 + (threadIdx.x >> 5);
    int lane = threadIdx.x & 31;
    if (r >= 32768) return;
    const float4* rowp = reinterpret_cast<const float4*>(df + (size_t)r * 512);
    const float4* wc4  = reinterpret_cast<const float4*>(Wc);
    float c0 = 0.0f, c1 = 0.0f;
    #pragma unroll
    for (int it = 0; it < 4; it++) {
        int k4 = it * 32 + lane;
        float4 d = rowp[k4];
        float4 a = wc4[k4 * 2];
        float4 b = wc4[k4 * 2 + 1];
        c0 = fmaf(d.x, a.x, c0); c1 = fmaf(d.x, a.y, c1);
        c0 = fmaf(d.y, a.z, c0); c1 = fmaf(d.y, a.w, c1);
        c0 = fmaf(d.z, b.x, c0); c1 = fmaf(d.z, b.y, c1);
        c0 = fmaf(d.w, b.z, c0); c1 = fmaf(d.w, b.w, c1);
    }
    #pragma unroll
    for (int o = 16; o; o >>= 1) {
        c0 += __shfl_xor_sync(0xffffffffu, c0, o);
        c1 += __shfl_xor_sync(0xffffffffu, c1, o);
    }
    if (lane == 0) {
        coords[(size_t)r * 2]     = c0 + bc[0];
        coords[(size_t)r * 2 + 1] = c1 + bc[1];
    }
}

// ---------------- importance: row L2 norm (1027 of 1152-stride), float4 ----------------
__global__ void __launch_bounds__(256) imp_k(
    const float* __restrict__ ef, float* __restrict__ imp)
{
    int r    = blockIdx.x * 8 + (threadIdx.x >> 5);
    int lane = threadIdx.x & 31;
    if (r >= 32768) return;
    const float4* rowp = reinterpret_cast<const float4*>(ef + (size_t)r * 1152);
    float s = 0.0f;
    #pragma unroll
    for (int it = 0; it < 8; it++) {
        float4 v = rowp[it * 32 + lane];
        s = fmaf(v.x, v.x, s);
        s = fmaf(v.y, v.y, s);
        s = fmaf(v.z, v.z, s);
        s = fmaf(v.w, v.w, s);
    }
    if (lane < 3) {
        float v = ef[(size_t)r * 1152 + 1024 + lane];
        s = fmaf(v, v, s);
    }
    #pragma unroll
    for (int o = 16; o; o >>= 1) s += __shfl_xor_sync(0xffffffffu, s, o);
    if (lane == 0) imp[r] = sqrtf(s);
}

// ---------------- top-512 of 4096 per batch ----------------
__global__ void __launch_bounds__(1024) topk_k(
    const float* __restrict__ imp, int* __restrict__ top)
{
    __shared__ unsigned long long key[4096];
    int b   = blockIdx.x;
    int tid = threadIdx.x;
    for (int s = tid; s < 4096; s += 1024) {
        unsigned int bits = __float_as_uint(imp[b * 4096 + s]);
        key[s] = ((unsigned long long)(~bits) << 32) | (unsigned int)s;
    }
    for (int k = 2; k <= 4096; k <<= 1) {
        for (int j = k >> 1; j > 0; j >>= 1) {
            __syncthreads();
            for (int idx = tid; idx < 4096; idx += 1024) {
                int l = idx ^ j;
                if (l > idx) {
                    bool asc = ((idx & k) == 0);
                    unsigned long long a = key[idx], c = key[l];
                    if ((a > c) == asc) { key[idx] = c; key[l] = a; }
                }
            }
        }
    }
    __syncthreads();
    if (tid < 512) top[b * 512 + tid] = (int)(key[tid] & 0xffffffffu);
}

// ---------------- gather selected rows (1152-stride source) ----------------
__global__ void __launch_bounds__(256) gather_k(
    const float* __restrict__ ef, const int* __restrict__ top,
    float* __restrict__ pos, float* __restrict__ states)
{
    int rowi = blockIdx.x;
    int b    = rowi >> 9;
    int s    = top[rowi];
    const float* src = ef + (size_t)(b * 4096 + s) * 1152;
    if (threadIdx.x < 2) pos[rowi * 2 + threadIdx.x] = src[threadIdx.x];
    for (int d = threadIdx.x; d < 1024; d += 256)
        states[(size_t)rowi * 1024 + d] = src[2 + d];
}

// ---------------- separable exp tables ----------------
__global__ void __launch_bounds__(512) exptab_k(
    const float* __restrict__ pos, float* __restrict__ ex, float* __restrict__ ey)
{
    int g = blockIdx.x;
    int b = blockIdx.y;
    int n = threadIdx.x;
    float gv = (g == 99) ? 1.0f : -1.0f + (float)g * (2.0f / 99.0f);
    float px = pos[(b * 512 + n) * 2];
    float py = pos[(b * 512 + n) * 2 + 1];
    float dx = gv - px;
    float dy = gv - py;
    size_t o = ((size_t)b * 100 + g) * 512 + n;
    ex[o] = __expf(dx * dx * -10.0f);
    ey[o] = __expf(dy * dy * -10.0f);
}

// ---------------- fused gaussian attention + einsum (separable exp) ----------------
__global__ void __launch_bounds__(256, 2) attn_k(
    const float* __restrict__ ex, const float* __restrict__ ey,
    const float* __restrict__ proj, float* __restrict__ out)
{
    extern __shared__ float sm[];
    float* sa   = sm;                  // 32*512
    float* rinv = sa + 32 * 512;       // 32

    const int b   = blockIdx.y;
    const int g0  = blockIdx.x * 32;
    const int tid = threadIdx.x;

    const float* exb = ex + (size_t)b * 100 * 512;
    const float* eyb = ey + (size_t)b * 100 * 512;

    for (int e = tid; e < 32 * 512; e += 256) {
        int i  = e >> 9;
        int n  = e & 511;
        int gi = g0 + i;
        float a = 0.0f;
        if (gi < 10000) {
            int ix = gi / 100, iy = gi - ix * 100;
            a = exb[(size_t)ix * 512 + n] * eyb[(size_t)iy * 512 + n];
        }
        sa[i * 512 + n] = a;
    }
    __syncthreads();

    int warp = tid >> 5, lane = tid & 31;
    for (int i = warp; i < 32; i += 8) {
        float s = 0.0f;
        for (int n = lane; n < 512; n += 32) s += sa[i * 512 + n];
        #pragma unroll
        for (int o = 16; o; o >>= 1) s += __shfl_xor_sync(0xffffffffu, s, o);
        if (lane == 0) rinv[i] = 1.0f / (s + 1e-8f);
    }
    __syncthreads();

    const int gg = tid >> 6;           // 0..3 -> rows gg*8..+7
    const int dt = tid & 63;           // cols dt*8..+7
    const float* pb   = proj + (size_t)b * 512 * 512 + dt * 8;
    const float* saro = sa + gg * 8 * 512;
    unsigned long long acc[8][4];
    #pragma unroll
    for (int i = 0; i < 8; i++)
        #pragma unroll
        for (int p = 0; p < 4; p++) acc[i][p] = 0ULL;

    for (int n = 0; n < 512; n++) {
        ulonglong2 v0 = *reinterpret_cast<const ulonglong2*>(pb + (size_t)n * 512);
        ulonglong2 v1 = *reinterpret_cast<const ulonglong2*>(pb + (size_t)n * 512 + 4);
        #pragma unroll
        for (int i = 0; i < 8; i++) {
            unsigned long long pa = pack2(saro[i * 512 + n]);
            fma2(acc[i][0], pa, v0.x);
            fma2(acc[i][1], pa, v0.y);
            fma2(acc[i][2], pa, v1.x);
            fma2(acc[i][3], pa, v1.y);
        }
    }

    #pragma unroll
    for (int i = 0; i < 8; i++) {
        int gi = g0 + gg * 8 + i;
        if (gi < 10000) {
            float r = rinv[gg * 8 + i];
            float* o = out + ((size_t)b * 10000 + gi) * 512 + dt * 8;
            float2 t0 = unpack2(acc[i][0]);
            float2 t1 = unpack2(acc[i][1]);
            float2 t2 = unpack2(acc[i][2]);
            float2 t3 = unpack2(acc[i][3]);
            float4 v;
            v.x = t0.x * r; v.y = t0.y * r; v.z = t1.x * r; v.w = t1.y * r;
            *reinterpret_cast<float4*>(o) = v;
            v.x = t2.x * r; v.y = t2.y * r; v.z = t3.x * r; v.w = t3.y * r;
            *reinterpret_cast<float4*>(o + 4) = v;
        }
    }
}

// ---------------- launch ----------------
extern "C" void kernel_launch(void* const* d_in, const int* in_sizes, int n_in,
                              void* d_out, int out_size)
{
    const float* x   = (const float*)d_in[0];
    const float* W1  = (const float*)d_in[1];
    const float* b1  = (const float*)d_in[2];
    const float* W2  = (const float*)d_in[3];
    const float* b2  = (const float*)d_in[4];
    const float* Wc  = (const float*)d_in[5];
    const float* bc  = (const float*)d_in[6];
    const float* We1 = (const float*)d_in[7];
    const float* be1 = (const float*)d_in[8];
    const float* We2 = (const float*)d_in[9];
    const float* be2 = (const float*)d_in[10];
    const float* Wo1 = (const float*)d_in[11];
    const float* bo1 = (const float*)d_in[12];
    const float* Wo2 = (const float*)d_in[13];
    const float* bo2 = (const float*)d_in[14];
    float* out = (float*)d_out;

    float *h1, *df, *ef, *coords, *imp, *pos, *states, *proj, *We2p, *be2p, *ex, *ey;
    int* top;
    cudaGetSymbolAddress((void**)&h1,     g_h1);
    cudaGetSymbolAddress((void**)&df,     g_df);
    cudaGetSymbolAddress((void**)&ef,     g_ef);
    cudaGetSymbolAddress((void**)&coords, g_coords);
    cudaGetSymbolAddress((void**)&imp,    g_imp);
    cudaGetSymbolAddress((void**)&top,    g_top);
    cudaGetSymbolAddress((void**)&pos,    g_pos);
    cudaGetSymbolAddress((void**)&states, g_states);
    cudaGetSymbolAddress((void**)&proj,   g_proj);
    cudaGetSymbolAddress((void**)&We2p,   g_We2p);
    cudaGetSymbolAddress((void**)&be2p,   g_be2p);
    cudaGetSymbolAddress((void**)&ex,     g_ex);
    cudaGetSymbolAddress((void**)&ey,     g_ey);

    // order chosen so the 4th launch (the one ncu profiles) is the stage-4 GEMM
    // 1) h1 = gelu(x @ W1 + b1)
    gemm_k<1><<<dim3(8,256), 256>>>(x,  W1, b1, h1, 32768, 512, 512, 512, 512, nullptr, nullptr);
    // 2) df = gelu(h1 @ W2 + b2)
    gemm_k<1><<<dim3(8,256), 256>>>(h1, W2, b2, df, 32768, 512, 512, 512, 512, nullptr, nullptr);
    // 3) coords = df @ Wc + bc
    coords_k<<<4096, 256>>>(df, Wc, bc, coords);
    // 4) h1 = gelu(df @ We1[2:,:] + coords @ We1[:2,:] + be1)   <-- profiled
    gemm_k<2><<<dim3(8,256), 256>>>(df, We1 + 1024, be1, h1, 32768, 512, 512, 512, 512, coords, We1);
    // 5) pad We2 -> (512,1152), be2 -> 1152
    padB_k<<<2304, 256>>>(We2, We2p, be2, be2p);
    // 6) ef = h1 @ We2p + be2p   (N=1152 padded)
    gemm_k<0><<<dim3(18,256), 256>>>(h1, We2p, be2p, ef, 32768, 1152, 512, 512, 1152, nullptr, nullptr);
    // 7) importance
    imp_k<<<4096, 256>>>(ef, imp);
    // 8) top-512 per batch
    topk_k<<<8, 1024>>>(imp, top);
    // 9) gather
    gather_k<<<4096, 256>>>(ef, top, pos, states);
    // 10) h1 = gelu(states @ Wo1 + bo1)   (4096,2048,1024)
    gemm_k<1><<<dim3(32,32), 256>>>(states, Wo1, bo1, h1, 4096, 2048, 1024, 1024, 2048, nullptr, nullptr);
    // 11) proj partials = h1 @ Wo2 split-K x2, then reduce+bias
    gemm_k<3><<<dim3(8,64), 256>>>(h1, Wo2, nullptr, ef, 4096, 512, 1024, 2048, 512, nullptr, nullptr);
    reduce10_k<<<2048, 256>>>(ef, bo2, proj);
    // 12) separable exp tables (depends on pos)
    exptab_k<<<dim3(100, 8), 512>>>(pos, ex, ey);
    // 13) fused gaussian attention + einsum
    cudaFuncSetAttribute(attn_k, cudaFuncAttributeMaxDynamicSharedMemorySize, 66688);
    attn_k<<<dim3(313, 8), 256, 65664>>>(ex, ey, proj, out);
}

// round 16
// speedup vs baseline: 1.2421x; 1.2421x over previous
#include <cuda_runtime.h>
#include <math.h>

// ---------------- scratch ----------------
__device__ float g_h1[16777216];      // 32768*512 (stage-4 hidden; also 4096*2048 for stage Wo1)
__device__ float g_df[16777216];      // 32768*512 (df; later h1_sel 4096*512)
__device__ float g_ef[37748736];      // z (32768*512) @0; split-K partials @0; ef_sel @20971520
__device__ float g_coords[65536];     // 32768*2
__device__ float g_imp[32768];
__device__ int   g_top[4096];         // 8*512
__device__ float g_pos[8192];         // 8*512*2
__device__ float g_states[4194304];   // 4096*1024
__device__ float g_proj[2097152];     // 4096*512
__device__ float g_We2p[589824];      // 512*1152 padded We2
__device__ float g_be2p[1152];        // padded be2
__device__ float g_We2T[589824];      // 1152*512 transpose of We2p
__device__ float g_G[262144];         // 512*512 Gram = We2 We2^T
__device__ float g_wb2[512];          // 2 * We2 @ be2
__device__ float g_zeros[512];
__device__ float g_bb[1];             // ||be2||^2
__device__ float g_ex[409600];        // 8*100*512 separable exp table (x)
__device__ float g_ey[409600];        // 8*100*512 separable exp table (y)

__device__ __forceinline__ float gelu_f(float x) {
    return 0.5f * x * (1.0f + erff(x * 0.70710678118654752440f));
}

// ---- packed fp32x2 helpers (bit-exact fp32) ----
__device__ __forceinline__ unsigned long long pack2(float x) {
    unsigned long long r;
    asm("mov.b64 %0, {%1, %1};" : "=l"(r) : "f"(x));
    return r;
}
__device__ __forceinline__ void fma2(unsigned long long& d,
                                     unsigned long long a,
                                     unsigned long long b) {
    asm("fma.rn.f32x2 %0, %1, %2, %0;" : "+l"(d) : "l"(a), "l"(b));
}
__device__ __forceinline__ float2 unpack2(unsigned long long p) {
    float2 f;
    asm("mov.b64 {%0, %1}, %2;" : "=f"(f.x), "=f"(f.y) : "l"(p));
    return f;
}

// ---------------- pad We2 (512,1027) -> (512,1152), be2 -> 1152, zero g_zeros ----------------
__global__ void __launch_bounds__(256) padB_k(const float* __restrict__ src,
                                              float* __restrict__ dst,
                                              const float* __restrict__ bsrc,
                                              float* __restrict__ bdst,
                                              float* __restrict__ zdst)
{
    int i = blockIdx.x * 256 + threadIdx.x;
    if (i < 1152) bdst[i] = (i < 1027) ? bsrc[i] : 0.0f;
    if (i < 512)  zdst[i] = 0.0f;
    if (i >= 512 * 1152) return;
    int r = i / 1152, c = i - r * 1152;
    dst[i] = (c < 1027) ? src[r * 1027 + c] : 0.0f;
}

// ---------------- transpose We2p (512x1152) -> We2T (1152x512) ----------------
__global__ void __launch_bounds__(256) transp_k(const float* __restrict__ src,
                                                float* __restrict__ dst)
{
    int i = blockIdx.x * 256 + threadIdx.x;
    if (i >= 1152 * 512) return;
    int n = i >> 9;          // 0..1151
    int r = i & 511;         // 0..511
    dst[i] = src[r * 1152 + n];
}

// ---------------- wb2[r] = 2 * sum_n We2[r][n]*be2[n];  bb = sum be2^2 ----------------
__global__ void __launch_bounds__(256) wb_k(const float* __restrict__ We2,
                                            const float* __restrict__ be2,
                                            float* __restrict__ wb2,
                                            float* __restrict__ bb)
{
    int r    = blockIdx.x * 8 + (threadIdx.x >> 5);
    int lane = threadIdx.x & 31;
    if (r < 512) {
        const float* row = We2 + (size_t)r * 1027;
        float s = 0.0f;
        for (int n = lane; n < 1027; n += 32) s = fmaf(row[n], be2[n], s);
        #pragma unroll
        for (int o = 16; o; o >>= 1) s += __shfl_xor_sync(0xffffffffu, s, o);
        if (lane == 0) wb2[r] = 2.0f * s;
    }
    if (blockIdx.x == 0 && (threadIdx.x >> 5) == 0) {
        float s = 0.0f;
        for (int n = lane; n < 1027; n += 32) s = fmaf(be2[n], be2[n], s);
        #pragma unroll
        for (int o = 16; o; o >>= 1) s += __shfl_xor_sync(0xffffffffu, s, o);
        if (lane == 0) *bb = s;
    }
}

// ---------------- tiled fp32 GEMM, 128x128x32, 8x8/thread, FFMA2, double-buffered (R14) ----------------
// EPI: 0 = +bias, 1 = gelu(+bias), 2 = gelu(+bias + coords@wtop), 3 = split-K x2 raw partial
#define AS2(BF,KK,II) As2p[(((BF) * 32 + (KK)) * 130) + (II)]
#define BSF(BF,KK,II) Bsp[(((BF) * 32 + (KK)) * 128) + (II)]

#define GEMM_PREFETCH(KN)                                                                       \
    do {                                                                                        \
        ra0 = *reinterpret_cast<const float4*>(A + (size_t)(bm + rA0) * lda + (KN) + cA4 * 4);  \
        ra1 = *reinterpret_cast<const float4*>(A + (size_t)(bm + rA0 + 64) * lda + (KN) + cA4 * 4); \
        rb0 = *reinterpret_cast<const float4*>(B + (size_t)((KN) + rB0) * ldb + bn + cB);       \
        rb1 = *reinterpret_cast<const float4*>(B + (size_t)((KN) + rB0 + 8) * ldb + bn + cB);   \
    } while (0)

#define GEMM_STORE(BUF, H)                                                                      \
    do {                                                                                        \
        AS2(BUF, (H) + cA4 * 4 + 0, rA0) = pack2(ra0.x);                                        \
        AS2(BUF, (H) + cA4 * 4 + 1, rA0) = pack2(ra0.y);                                        \
        AS2(BUF, (H) + cA4 * 4 + 2, rA0) = pack2(ra0.z);                                        \
        AS2(BUF, (H) + cA4 * 4 + 3, rA0) = pack2(ra0.w);                                        \
        AS2(BUF, (H) + cA4 * 4 + 0, rA0 + 64) = pack2(ra1.x);                                   \
        AS2(BUF, (H) + cA4 * 4 + 1, rA0 + 64) = pack2(ra1.y);                                   \
        AS2(BUF, (H) + cA4 * 4 + 2, rA0 + 64) = pack2(ra1.z);                                   \
        AS2(BUF, (H) + cA4 * 4 + 3, rA0 + 64) = pack2(ra1.w);                                   \
        *reinterpret_cast<float4*>(&BSF(BUF, (H) + rB0, cB))     = rb0;                         \
        *reinterpret_cast<float4*>(&BSF(BUF, (H) + rB0 + 8, cB)) = rb1;                         \
    } while (0)

#define GEMM_COMPUTE(BUF, H)                                                                    \
    do {                                                                                        \
        _Pragma("unroll")                                                                       \
        for (int k = 0; k < 16; k++) {                                                          \
            ulonglong2 A0 = *reinterpret_cast<const ulonglong2*>(&AS2(BUF, (H) + k, row));      \
            ulonglong2 A1 = *reinterpret_cast<const ulonglong2*>(&AS2(BUF, (H) + k, row + 2));  \
            ulonglong2 A2 = *reinterpret_cast<const ulonglong2*>(&AS2(BUF, (H) + k, row + 4));  \
            ulonglong2 A3 = *reinterpret_cast<const ulonglong2*>(&AS2(BUF, (H) + k, row + 6));  \
            ulonglong2 B0 = *reinterpret_cast<const ulonglong2*>(&BSF(BUF, (H) + k, tx * 4));   \
            ulonglong2 B1 = *reinterpret_cast<const ulonglong2*>(&BSF(BUF, (H) + k, 64 + tx * 4)); \
            fma2(acc2[0][0], A0.x, B0.x); fma2(acc2[0][1], A0.x, B0.y);                         \
            fma2(acc2[0][2], A0.x, B1.x); fma2(acc2[0][3], A0.x, B1.y);                         \
            fma2(acc2[1][0], A0.y, B0.x); fma2(acc2[1][1], A0.y, B0.y);                         \
            fma2(acc2[1][2], A0.y, B1.x); fma2(acc2[1][3], A0.y, B1.y);                         \
            fma2(acc2[2][0], A1.x, B0.x); fma2(acc2[2][1], A1.x, B0.y);                         \
            fma2(acc2[2][2], A1.x, B1.x); fma2(acc2[2][3], A1.x, B1.y);                         \
            fma2(acc2[3][0], A1.y, B0.x); fma2(acc2[3][1], A1.y, B0.y);                         \
            fma2(acc2[3][2], A1.y, B1.x); fma2(acc2[3][3], A1.y, B1.y);                         \
            fma2(acc2[4][0], A2.x, B0.x); fma2(acc2[4][1], A2.x, B0.y);                         \
            fma2(acc2[4][2], A2.x, B1.x); fma2(acc2[4][3], A2.x, B1.y);                         \
            fma2(acc2[5][0], A2.y, B0.x); fma2(acc2[5][1], A2.y, B0.y);                         \
            fma2(acc2[5][2], A2.y, B1.x); fma2(acc2[5][3], A2.y, B1.y);                         \
            fma2(acc2[6][0], A3.x, B0.x); fma2(acc2[6][1], A3.x, B0.y);                         \
            fma2(acc2[6][2], A3.x, B1.x); fma2(acc2[6][3], A3.x, B1.y);                         \
            fma2(acc2[7][0], A3.y, B0.x); fma2(acc2[7][1], A3.y, B0.y);                         \
            fma2(acc2[7][2], A3.y, B1.x); fma2(acc2[7][3], A3.y, B1.y);                         \
        }                                                                                       \
    } while (0)

static const int GEMM_SMEM = 2 * 32 * 130 * 8 + 2 * 32 * 128 * 4;   // 99328 B

template<int EPI>
__global__ void __launch_bounds__(256, 2) gemm_k(
    const float* __restrict__ A, const float* __restrict__ B,
    const float* __restrict__ bias, float* __restrict__ C,
    int M, int N, int K, int lda, int ldb,
    const float* __restrict__ coords, const float* __restrict__ wtop)
{
    extern __shared__ __align__(16) char smbuf[];
    unsigned long long* As2p = reinterpret_cast<unsigned long long*>(smbuf);
    float* Bsp = reinterpret_cast<float*>(smbuf + 2 * 32 * 130 * 8);

    const int tid = threadIdx.x;
    int bm, bn;
    if (EPI == 3) {
        const int half = blockIdx.y >> 5;
        bm = (blockIdx.y & 31) * 128;
        bn = blockIdx.x * 128;
        A += (size_t)half * 1024;                 // lda covers the full row
        B += (size_t)half * 1024 * ldb;
        C += (size_t)half * 2097152;              // 4096*512 partial stride
    } else {
        bm = blockIdx.y * 128;
        bn = blockIdx.x * 128;
    }
    const int tx  = tid & 15;
    const int ty  = tid >> 4;
    const int row = ty * 8;

    unsigned long long acc2[8][4];
    #pragma unroll
    for (int i = 0; i < 8; i++)
        #pragma unroll
        for (int p = 0; p < 4; p++) acc2[i][p] = 0ULL;

    const int rA0 = tid >> 2;
    const int cA4 = tid & 3;
    const int rB0 = tid >> 5;
    const int cB  = (tid & 31) * 4;

    float4 ra0, ra1, rb0, rb1;

    GEMM_PREFETCH(0);
    GEMM_STORE(0, 0);
    GEMM_PREFETCH(16);
    GEMM_STORE(0, 16);
    __syncthreads();

    const int T32 = K >> 5;        // even for all our K (512 -> 16, 1024 -> 32, 1152 -> 36)
    for (int t = 0; t < T32; t += 2) {
        GEMM_PREFETCH((t + 1) * 32);
        GEMM_COMPUTE(0, 0);
        GEMM_STORE(1, 0);
        GEMM_PREFETCH((t + 1) * 32 + 16);
        GEMM_COMPUTE(0, 16);
        GEMM_STORE(1, 16);
        __syncthreads();
        if (t + 2 < T32) {
            GEMM_PREFETCH((t + 2) * 32);
            GEMM_COMPUTE(1, 0);
            GEMM_STORE(0, 0);
            GEMM_PREFETCH((t + 2) * 32 + 16);
            GEMM_COMPUTE(1, 16);
            GEMM_STORE(0, 16);
            __syncthreads();
        } else {
            GEMM_COMPUTE(1, 0);
            GEMM_COMPUTE(1, 16);
        }
    }

    float acc[8][8];
    #pragma unroll
    for (int i = 0; i < 8; i++)
        #pragma unroll
        for (int p = 0; p < 4; p++) {
            float2 t = unpack2(acc2[i][p]);
            acc[i][p * 2 + 0] = t.x;
            acc[i][p * 2 + 1] = t.y;
        }

    float bs[8], w0[8], w1[8];
    #pragma unroll
    for (int h = 0; h < 2; h++)
        #pragma unroll
        for (int jj = 0; jj < 4; jj++) {
            int j = h * 4 + jj;
            int n = bn + h * 64 + tx * 4 + jj;
            bs[j] = (EPI == 3) ? 0.0f : bias[n];
            if (EPI == 2) { w0[j] = wtop[n]; w1[j] = wtop[512 + n]; }
        }

    #pragma unroll
    for (int i = 0; i < 8; i++) {
        int gm = bm + row + i;
        float c0 = 0.0f, c1 = 0.0f;
        if (EPI == 2) { c0 = coords[(size_t)gm * 2]; c1 = coords[(size_t)gm * 2 + 1]; }
        #pragma unroll
        for (int h = 0; h < 2; h++) {
            int nb = bn + h * 64 + tx * 4;
            float t[4];
            #pragma unroll
            for (int jj = 0; jj < 4; jj++) {
                int j = h * 4 + jj;
                float val = acc[i][j] + bs[j];
                if (EPI == 2) val += c0 * w0[j] + c1 * w1[j];
                if (EPI == 1 || EPI == 2) val = gelu_f(val);
                t[jj] = val;
            }
            float4 v; v.x = t[0]; v.y = t[1]; v.z = t[2]; v.w = t[3];
            *reinterpret_cast<float4*>(C + (size_t)gm * N + nb) = v;
        }
    }
}

// ---------------- split-K reduce: proj = p0 + p1 + bo2 ----------------
__global__ void __launch_bounds__(256) reduce10_k(
    const float* __restrict__ parts, const float* __restrict__ bias,
    float* __restrict__ proj)
{
    int i4 = blockIdx.x * 256 + threadIdx.x;
    if (i4 >= 524288) return;
    const float4* p0 = reinterpret_cast<const float4*>(parts);
    const float4* p1 = reinterpret_cast<const float4*>(parts + 2097152);
    const float4* b4 = reinterpret_cast<const float4*>(bias);
    float4 a = p0[i4];
    float4 b = p1[i4];
    float4 c = b4[i4 & 127];
    float4 v;
    v.x = a.x + b.x + c.x;
    v.y = a.y + b.y + c.y;
    v.z = a.z + b.z + c.z;
    v.w = a.w + b.w + c.w;
    reinterpret_cast<float4*>(proj)[i4] = v;
}

// ---------------- coords: (32768,512) @ (512,2) + bc, float4 ----------------
__global__ void __launch_bounds__(256) coords_k(
    const float* __restrict__ df, const float* __restrict__ Wc,
    const float* __restrict__ bc, float* __restrict__ coords)
{
    int r    = blockIdx.x * 8 + (threadIdx.x >> 5);
    int lane = threadIdx.x & 31;
    if (r >= 32768) return;
    const float4* rowp = reinterpret_cast<const float4*>(df + (size_t)r * 512);
    const float4* wc4  = reinterpret_cast<const float4*>(Wc);
    float c0 = 0.0f, c1 = 0.0f;
    #pragma unroll
    for (int it = 0; it < 4; it++) {
        int k4 = it * 32 + lane;
        float4 d = rowp[k4];
        float4 a = wc4[k4 * 2];
        float4 b = wc4[k4 * 2 + 1];
        c0 = fmaf(d.x, a.x, c0); c1 = fmaf(d.x, a.y, c1);
        c0 = fmaf(d.y, a.z, c0); c1 = fmaf(d.y, a.w, c1);
        c0 = fmaf(d.z, b.x, c0); c1 = fmaf(d.z, b.y, c1);
        c0 = fmaf(d.w, b.z, c0); c1 = fmaf(d.w, b.w, c1);
    }
    #pragma unroll
    for (int o = 16; o; o >>= 1) {
        c0 += __shfl_xor_sync(0xffffffffu, c0, o);
        c1 += __shfl_xor_sync(0xffffffffu, c1, o);
    }
    if (lane == 0) {
        coords[(size_t)r * 2]     = c0 + bc[0];
        coords[(size_t)r * 2 + 1] = c1 + bc[1];
    }
}

// ---------------- imp[r] = sqrt( dot(h1[r], z[r]) + bb ) ----------------
__global__ void __launch_bounds__(256) imp2_k(
    const float* __restrict__ h1, const float* __restrict__ z,
    const float* __restrict__ bb, float* __restrict__ imp)
{
    int r    = blockIdx.x * 8 + (threadIdx.x >> 5);
    int lane = threadIdx.x & 31;
    if (r >= 32768) return;
    const float4* a = reinterpret_cast<const float4*>(h1 + (size_t)r * 512);
    const float4* c = reinterpret_cast<const float4*>(z + (size_t)r * 512);
    float s = 0.0f;
    #pragma unroll
    for (int it = 0; it < 4; it++) {
        int k4 = it * 32 + lane;
        float4 x = a[k4];
        float4 y = c[k4];
        s = fmaf(x.x, y.x, s);
        s = fmaf(x.y, y.y, s);
        s = fmaf(x.z, y.z, s);
        s = fmaf(x.w, y.w, s);
    }
    #pragma unroll
    for (int o = 16; o; o >>= 1) s += __shfl_xor_sync(0xffffffffu, s, o);
    if (lane == 0) imp[r] = sqrtf(s + *bb);
}

// ---------------- top-512 of 4096 per batch ----------------
__global__ void __launch_bounds__(1024) topk_k(
    const float* __restrict__ imp, int* __restrict__ top)
{
    __shared__ unsigned long long key[4096];
    int b   = blockIdx.x;
    int tid = threadIdx.x;
    for (int s = tid; s < 4096; s += 1024) {
        unsigned int bits = __float_as_uint(imp[b * 4096 + s]);
        key[s] = ((unsigned long long)(~bits) << 32) | (unsigned int)s;
    }
    for (int k = 2; k <= 4096; k <<= 1) {
        for (int j = k >> 1; j > 0; j >>= 1) {
            __syncthreads();
            for (int idx = tid; idx < 4096; idx += 1024) {
                int l = idx ^ j;
                if (l > idx) {
                    bool asc = ((idx & k) == 0);
                    unsigned long long a = key[idx], c = key[l];
                    if ((a > c) == asc) { key[idx] = c; key[l] = a; }
                }
            }
        }
    }
    __syncthreads();
    if (tid < 512) top[b * 512 + tid] = (int)(key[tid] & 0xffffffffu);
}

// ---------------- gather selected h1 rows -> h1_sel (4096x512) ----------------
__global__ void __launch_bounds__(128) gatherh_k(
    const float* __restrict__ h1, const int* __restrict__ top,
    float* __restrict__ h1sel)
{
    int rowi = blockIdx.x;
    int b    = rowi >> 9;
    int s    = top[rowi];
    const float4* src = reinterpret_cast<const float4*>(h1 + (size_t)(b * 4096 + s) * 512);
    float4* dst = reinterpret_cast<float4*>(h1sel + (size_t)rowi * 512);
    dst[threadIdx.x] = src[threadIdx.x];
}

// ---------------- split ef_sel (4096x1152, selected order) -> pos, states ----------------
__global__ void __launch_bounds__(256) gather_k(
    const float* __restrict__ efsel,
    float* __restrict__ pos, float* __restrict__ states)
{
    int rowi = blockIdx.x;
    const float* src = efsel + (size_t)rowi * 1152;
    if (threadIdx.x < 2) pos[rowi * 2 + threadIdx.x] = src[threadIdx.x];
    for (int d = threadIdx.x; d < 1024; d += 256)
        states[(size_t)rowi * 1024 + d] = src[2 + d];
}

// ---------------- separable exp tables ----------------
__global__ void __launch_bounds__(512) exptab_k(
    const float* __restrict__ pos, float* __restrict__ ex, float* __restrict__ ey)
{
    int g = blockIdx.x;
    int b = blockIdx.y;
    int n = threadIdx.x;
    float gv = (g == 99) ? 1.0f : -1.0f + (float)g * (2.0f / 99.0f);
    float px = pos[(b * 512 + n) * 2];
    float py = pos[(b * 512 + n) * 2 + 1];
    float dx = gv - px;
    float dy = gv - py;
    size_t o = ((size_t)b * 100 + g) * 512 + n;
    ex[o] = __expf(dx * dx * -10.0f);
    ey[o] = __expf(dy * dy * -10.0f);
}

// ---------------- fused gaussian attention + einsum (separable exp) ----------------
__global__ void __launch_bounds__(256, 2) attn_k(
    const float* __restrict__ ex, const float* __restrict__ ey,
    const float* __restrict__ proj, float* __restrict__ out)
{
    extern __shared__ float sm[];
    float* sa   = sm;                  // 32*512
    float* rinv = sa + 32 * 512;       // 32

    const int b   = blockIdx.y;
    const int g0  = blockIdx.x * 32;
    const int tid = threadIdx.x;

    const float* exb = ex + (size_t)b * 100 * 512;
    const float* eyb = ey + (size_t)b * 100 * 512;

    for (int e = tid; e < 32 * 512; e += 256) {
        int i  = e >> 9;
        int n  = e & 511;
        int gi = g0 + i;
        float a = 0.0f;
        if (gi < 10000) {
            int ix = gi / 100, iy = gi - ix * 100;
            a = exb[(size_t)ix * 512 + n] * eyb[(size_t)iy * 512 + n];
        }
        sa[i * 512 + n] = a;
    }
    __syncthreads();

    int warp = tid >> 5, lane = tid & 31;
    for (int i = warp; i < 32; i += 8) {
        float s = 0.0f;
        for (int n = lane; n < 512; n += 32) s += sa[i * 512 + n];
        #pragma unroll
        for (int o = 16; o; o >>= 1) s += __shfl_xor_sync(0xffffffffu, s, o);
        if (lane == 0) rinv[i] = 1.0f / (s + 1e-8f);
    }
    __syncthreads();

    const int gg = tid >> 6;           // 0..3 -> rows gg*8..+7
    const int dt = tid & 63;           // cols dt*8..+7
    const float* pb   = proj + (size_t)b * 512 * 512 + dt * 8;
    const float* saro = sa + gg * 8 * 512;
    unsigned long long acc[8][4];
    #pragma unroll
    for (int i = 0; i < 8; i++)
        #pragma unroll
        for (int p = 0; p < 4; p++) acc[i][p] = 0ULL;

    for (int n = 0; n < 512; n++) {
        ulonglong2 v0 = *reinterpret_cast<const ulonglong2*>(pb + (size_t)n * 512);
        ulonglong2 v1 = *reinterpret_cast<const ulonglong2*>(pb + (size_t)n * 512 + 4);
        #pragma unroll
        for (int i = 0; i < 8; i++) {
            unsigned long long pa = pack2(saro[i * 512 + n]);
            fma2(acc[i][0], pa, v0.x);
            fma2(acc[i][1], pa, v0.y);
            fma2(acc[i][2], pa, v1.x);
            fma2(acc[i][3], pa, v1.y);
        }
    }

    #pragma unroll
    for (int i = 0; i < 8; i++) {
        int gi = g0 + gg * 8 + i;
        if (gi < 10000) {
            float r = rinv[gg * 8 + i];
            float* o = out + ((size_t)b * 10000 + gi) * 512 + dt * 8;
            float2 t0 = unpack2(acc[i][0]);
            float2 t1 = unpack2(acc[i][1]);
            float2 t2 = unpack2(acc[i][2]);
            float2 t3 = unpack2(acc[i][3]);
            float4 v;
            v.x = t0.x * r; v.y = t0.y * r; v.z = t1.x * r; v.w = t1.y * r;
            *reinterpret_cast<float4*>(o) = v;
            v.x = t2.x * r; v.y = t2.y * r; v.z = t3.x * r; v.w = t3.y * r;
            *reinterpret_cast<float4*>(o + 4) = v;
        }
    }
}

// ---------------- launch ----------------
extern "C" void kernel_launch(void* const* d_in, const int* in_sizes, int n_in,
                              void* d_out, int out_size)
{
    const float* x   = (const float*)d_in[0];
    const float* W1  = (const float*)d_in[1];
    const float* b1  = (const float*)d_in[2];
    const float* W2  = (const float*)d_in[3];
    const float* b2  = (const float*)d_in[4];
    const float* Wc  = (const float*)d_in[5];
    const float* bc  = (const float*)d_in[6];
    const float* We1 = (const float*)d_in[7];
    const float* be1 = (const float*)d_in[8];
    const float* We2 = (const float*)d_in[9];
    const float* be2 = (const float*)d_in[10];
    const float* Wo1 = (const float*)d_in[11];
    const float* bo1 = (const float*)d_in[12];
    const float* Wo2 = (const float*)d_in[13];
    const float* bo2 = (const float*)d_in[14];
    float* out = (float*)d_out;

    float *h1, *df, *ef, *coords, *imp, *pos, *states, *proj, *We2p, *be2p;
    float *We2T, *G, *wb2, *zeros, *bb, *ex, *ey;
    int* top;
    cudaGetSymbolAddress((void**)&h1,     g_h1);
    cudaGetSymbolAddress((void**)&df,     g_df);
    cudaGetSymbolAddress((void**)&ef,     g_ef);
    cudaGetSymbolAddress((void**)&coords, g_coords);
    cudaGetSymbolAddress((void**)&imp,    g_imp);
    cudaGetSymbolAddress((void**)&top,    g_top);
    cudaGetSymbolAddress((void**)&pos,    g_pos);
    cudaGetSymbolAddress((void**)&states, g_states);
    cudaGetSymbolAddress((void**)&proj,   g_proj);
    cudaGetSymbolAddress((void**)&We2p,   g_We2p);
    cudaGetSymbolAddress((void**)&be2p,   g_be2p);
    cudaGetSymbolAddress((void**)&We2T,   g_We2T);
    cudaGetSymbolAddress((void**)&G,      g_G);
    cudaGetSymbolAddress((void**)&wb2,    g_wb2);
    cudaGetSymbolAddress((void**)&zeros,  g_zeros);
    cudaGetSymbolAddress((void**)&bb,     g_bb);
    cudaGetSymbolAddress((void**)&ex,     g_ex);
    cudaGetSymbolAddress((void**)&ey,     g_ey);

    float* z     = ef;                 // 32768*512 scratch (reuses g_ef)
    float* efsel = ef + 20971520;      // 4096*1152, clear of split-K partials @0

    cudaFuncSetAttribute(gemm_k<0>, cudaFuncAttributeMaxDynamicSharedMemorySize, GEMM_SMEM);
    cudaFuncSetAttribute(gemm_k<1>, cudaFuncAttributeMaxDynamicSharedMemorySize, GEMM_SMEM);
    cudaFuncSetAttribute(gemm_k<2>, cudaFuncAttributeMaxDynamicSharedMemorySize, GEMM_SMEM);
    cudaFuncSetAttribute(gemm_k<3>, cudaFuncAttributeMaxDynamicSharedMemorySize, GEMM_SMEM);

    // (4th launch = stage-4 GEMM, kept in profiler slot)
    // 1) h1 = gelu(x @ W1 + b1)
    gemm_k<1><<<dim3(4,256), 256, GEMM_SMEM>>>(x,  W1, b1, h1, 32768, 512, 512, 512, 512, nullptr, nullptr);
    // 2) df = gelu(h1 @ W2 + b2)
    gemm_k<1><<<dim3(4,256), 256, GEMM_SMEM>>>(h1, W2, b2, df, 32768, 512, 512, 512, 512, nullptr, nullptr);
    // 3) coords = df @ Wc + bc
    coords_k<<<4096, 256>>>(df, Wc, bc, coords);
    // 4) h1 = gelu(df @ We1[2:,:] + coords @ We1[:2,:] + be1)   <-- profiled
    gemm_k<2><<<dim3(4,256), 256, GEMM_SMEM>>>(df, We1 + 1024, be1, h1, 32768, 512, 512, 512, 512, coords, We1);
    // 5) pad We2 -> (512,1152), be2 -> 1152; zero g_zeros
    padB_k<<<2304, 256>>>(We2, We2p, be2, be2p, zeros);
    // 6) We2T = We2p^T
    transp_k<<<2304, 256>>>(We2p, We2T);
    // 7) wb2 = 2 * We2 @ be2;  bb = ||be2||^2
    wb_k<<<64, 256>>>(We2, be2, wb2, bb);
    // 8) G = We2p @ We2T  (512x512x1152)
    gemm_k<0><<<dim3(4,4), 256, GEMM_SMEM>>>(We2p, We2T, zeros, G, 512, 512, 1152, 1152, 512, nullptr, nullptr);
    // 9) z = h1 @ G + wb2  (32768x512x512)
    gemm_k<0><<<dim3(4,256), 256, GEMM_SMEM>>>(h1, G, wb2, z, 32768, 512, 512, 512, 512, nullptr, nullptr);
    // 10) imp[r] = sqrt(dot(h1[r], z[r]) + bb)
    imp2_k<<<4096, 256>>>(h1, z, bb, imp);
    // 11) top-512 per batch
    topk_k<<<8, 1024>>>(imp, top);
    // 12) gather selected h1 rows
    gatherh_k<<<4096, 128>>>(h1, top, df);
    // 13) ef_sel = h1_sel @ We2p + be2p  (4096x1152x512)
    gemm_k<0><<<dim3(9,32), 256, GEMM_SMEM>>>(df, We2p, be2p, efsel, 4096, 1152, 512, 512, 1152, nullptr, nullptr);
    // 14) split ef_sel -> pos, states
    gather_k<<<4096, 256>>>(efsel, pos, states);
    // 15) h1 = gelu(states @ Wo1 + bo1)   (4096,2048,1024)
    gemm_k<1><<<dim3(16,32), 256, GEMM_SMEM>>>(states, Wo1, bo1, h1, 4096, 2048, 1024, 1024, 2048, nullptr, nullptr);
    // 16) proj partials = h1 @ Wo2 split-K x2, then reduce+bias
    gemm_k<3><<<dim3(4,64), 256, GEMM_SMEM>>>(h1, Wo2, nullptr, ef, 4096, 512, 1024, 2048, 512, nullptr, nullptr);
    reduce10_k<<<2048, 256>>>(ef, bo2, proj);
    // 17) separable exp tables (depends on pos)
    exptab_k<<<dim3(100, 8), 512>>>(pos, ex, ey);
    // 18) fused gaussian attention + einsum
    cudaFuncSetAttribute(attn_k, cudaFuncAttributeMaxDynamicSharedMemorySize, 66688);
    attn_k<<<dim3(313, 8), 256, 65664>>>(ex, ey, proj, out);
}